// round 6
// baseline (speedup 1.0000x reference)
#include <cuda_runtime.h>
#include <cuda_bf16.h>
#include <cstdint>

// ---------------------------------------------------------------------------
// MHA: B=2, L=2048, D=1024, H=16, dh=64.
// R5: Q/K/V pre-converted to bf16 hi/lo in the projection GEMM epilogues
//     (Q pre-scaled, V pre-transposed). Attention inner loop = pure copies +
//     ldmatrix + mma + log2-softmax. 64 q-rows / 128 threads / 3 CTAs/SM.
// ---------------------------------------------------------------------------

namespace cfg {
constexpr int B = 2;
constexpr int L = 2048;
constexpr int D = 1024;
constexpr int H = 16;
constexpr int DH = 64;
constexpr int M = B * L;
constexpr int BH = B * H;
}

__device__ float g_A[(size_t)cfg::B * cfg::L * cfg::D];
// bf16 hi/lo pre-converted tensors.
__device__ __nv_bfloat16 g_Qh[(size_t)cfg::BH * cfg::L * cfg::DH];
__device__ __nv_bfloat16 g_Ql[(size_t)cfg::BH * cfg::L * cfg::DH];
__device__ __nv_bfloat16 g_Kh[(size_t)cfg::BH * cfg::L * cfg::DH];
__device__ __nv_bfloat16 g_Kl[(size_t)cfg::BH * cfg::L * cfg::DH];
__device__ __nv_bfloat16 g_Vth[(size_t)cfg::BH * cfg::DH * cfg::L];  // [dh][seq]
__device__ __nv_bfloat16 g_Vtl[(size_t)cfg::BH * cfg::DH * cfg::L];

// ======================= portable tensor-core helpers ======================
__device__ __forceinline__ uint32_t smem_u32(const void* p) {
  uint32_t a;
  asm("{ .reg .u64 t; cvta.to.shared.u64 t, %1; cvt.u32.u64 %0, t; }"
      : "=r"(a) : "l"(p));
  return a;
}

__device__ __forceinline__ void ldm_x4(uint32_t& r0, uint32_t& r1,
                                       uint32_t& r2, uint32_t& r3,
                                       uint32_t addr) {
  asm volatile("ldmatrix.sync.aligned.m8n8.x4.shared.b16 {%0,%1,%2,%3}, [%4];"
               : "=r"(r0), "=r"(r1), "=r"(r2), "=r"(r3) : "r"(addr));
}

__device__ __forceinline__ void mma_bf16(float* c, const uint32_t* a,
                                         const uint32_t* b) {
  asm volatile(
      "mma.sync.aligned.m16n8k16.row.col.f32.bf16.bf16.f32 "
      "{%0,%1,%2,%3}, {%4,%5,%6,%7}, {%8,%9}, {%0,%1,%2,%3};"
      : "+f"(c[0]), "+f"(c[1]), "+f"(c[2]), "+f"(c[3])
      : "r"(a[0]), "r"(a[1]), "r"(a[2]), "r"(a[3]), "r"(b[0]), "r"(b[1]));
}

__device__ __forceinline__ float fast_exp2(float x) {
  float y;
  asm("ex2.approx.f32 %0, %1;" : "=f"(y) : "f"(x));
  return y;
}

#define SW128(off) ((off) ^ ((((uint32_t)(off)) >> 3) & 0x70))

__device__ __forceinline__ uint32_t pack_bf2(float a, float b) {
  __nv_bfloat162 h = __floats2bfloat162_rn(a, b);
  return *(uint32_t*)&h;
}
__device__ __forceinline__ void pack_hl(float a, float b, uint32_t& hi,
                                        uint32_t& lo) {
  __nv_bfloat162 h = __floats2bfloat162_rn(a, b);
  hi = *(uint32_t*)&h;
  lo = pack_bf2(a - __bfloat162float(h.x), b - __bfloat162float(h.y));
}

// ---------------------------------------------------------------------------
// Projection GEMM: C = A @ W^T (mma.sync bf16x3). Epilogue modes:
//  0: fp32 C[M,1024]
//  1: bf16 hi/lo [b,h][seq][64], values scaled by `scale`
//  2: bf16 hi/lo transposed [b,h][dh][seq]
// ---------------------------------------------------------------------------
namespace goff {
constexpr int AHI = 0, ALO = 16384, BHI = 32768, BLO = 49152, TOTAL = 65536;
}

__global__ __launch_bounds__(256) void gemm_mma_kernel(
    const float* __restrict__ A, const float* __restrict__ W,
    float* __restrict__ C, __nv_bfloat16* __restrict__ outH,
    __nv_bfloat16* __restrict__ outL, int mode, float scale) {
  using namespace cfg;
  extern __shared__ char smem[];
  const uint32_t sb = smem_u32(smem);
  const int tid = threadIdx.x;
  const int wid = tid >> 5, lane = tid & 31;
  const int wm = wid & 3;
  const int wn = wid >> 2;
  const int bm = blockIdx.y << 7;
  const int bn = blockIdx.x << 7;

  const int lrow = tid >> 2;
  const int lk = (tid & 3) << 4;

  const float* Ap = A + (size_t)(bm + lrow) * D + lk;
  const float* Wp = W + (size_t)(bn + lrow) * D + lk;

  const uint32_t st0 = (uint32_t)lrow * 128 + (uint32_t)lk * 2;

  const int l7 = lane & 7;
  const uint32_t a_row_off = (uint32_t)(wm * 32 + l7 + ((lane >> 3) & 1) * 8) * 128;
  const uint32_t a_col_off = (uint32_t)((lane >> 4) * 16);
  const uint32_t b_row_off = (uint32_t)(wn * 64 + l7 + ((lane >> 4) & 1) * 8) * 128;
  const uint32_t b_col_off = (uint32_t)(((lane >> 3) & 1) * 16);

  float acc[2][8][4];
#pragma unroll
  for (int mt = 0; mt < 2; ++mt)
#pragma unroll
    for (int nt = 0; nt < 8; ++nt)
#pragma unroll
      for (int q = 0; q < 4; ++q) acc[mt][nt][q] = 0.0f;

  for (int ch = 0; ch < 16; ++ch) {
    const int k0 = ch << 6;

    float4 av[2][4], wv[2][4];
#pragma unroll
    for (int ri = 0; ri < 2; ++ri) {
      const float* ap = Ap + (size_t)ri * 64 * D + k0;
      const float* wp = Wp + (size_t)ri * 64 * D + k0;
#pragma unroll
      for (int i = 0; i < 4; ++i) {
        av[ri][i] = *(const float4*)(ap + i * 4);
        wv[ri][i] = *(const float4*)(wp + i * 4);
      }
    }

    __syncthreads();

#pragma unroll
    for (int ri = 0; ri < 2; ++ri) {
      const uint32_t so = st0 + (uint32_t)ri * 64 * 128;
#pragma unroll
      for (int half = 0; half < 2; ++half) {
        float4 v0a = av[ri][half * 2], v1a = av[ri][half * 2 + 1];
        float4 v0w = wv[ri][half * 2], v1w = wv[ri][half * 2 + 1];
        uint32_t off = SW128(so + half * 16);

        uint4 hi_a, lo_a, hi_w, lo_w;
        pack_hl(v0a.x, v0a.y, hi_a.x, lo_a.x);
        pack_hl(v0a.z, v0a.w, hi_a.y, lo_a.y);
        pack_hl(v1a.x, v1a.y, hi_a.z, lo_a.z);
        pack_hl(v1a.z, v1a.w, hi_a.w, lo_a.w);
        pack_hl(v0w.x, v0w.y, hi_w.x, lo_w.x);
        pack_hl(v0w.z, v0w.w, hi_w.y, lo_w.y);
        pack_hl(v1w.x, v1w.y, hi_w.z, lo_w.z);
        pack_hl(v1w.z, v1w.w, hi_w.w, lo_w.w);
        *(uint4*)(smem + goff::AHI + off) = hi_a;
        *(uint4*)(smem + goff::ALO + off) = lo_a;
        *(uint4*)(smem + goff::BHI + off) = hi_w;
        *(uint4*)(smem + goff::BLO + off) = lo_w;
      }
    }
    __syncthreads();

#pragma unroll
    for (int ks = 0; ks < 4; ++ks) {
      const uint32_t kc = (uint32_t)ks * 32;
      uint32_t ah[2][4], al[2][4], bh[4][4], bl[4][4];
#pragma unroll
      for (int mt = 0; mt < 2; ++mt) {
        uint32_t o = a_row_off + (uint32_t)mt * 16 * 128 + kc + a_col_off;
        uint32_t sw = SW128(o);
        ldm_x4(ah[mt][0], ah[mt][1], ah[mt][2], ah[mt][3], sb + goff::AHI + sw);
        ldm_x4(al[mt][0], al[mt][1], al[mt][2], al[mt][3], sb + goff::ALO + sw);
      }
#pragma unroll
      for (int p = 0; p < 4; ++p) {
        uint32_t o = b_row_off + (uint32_t)p * 16 * 128 + kc + b_col_off;
        uint32_t sw = SW128(o);
        ldm_x4(bh[p][0], bh[p][1], bh[p][2], bh[p][3], sb + goff::BHI + sw);
        ldm_x4(bl[p][0], bl[p][1], bl[p][2], bl[p][3], sb + goff::BLO + sw);
      }
#pragma unroll
      for (int mt = 0; mt < 2; ++mt)
#pragma unroll
        for (int nt = 0; nt < 8; ++nt) {
          const uint32_t* bhp = &bh[nt >> 1][(nt & 1) * 2];
          const uint32_t* blp = &bl[nt >> 1][(nt & 1) * 2];
          mma_bf16(acc[mt][nt], ah[mt], bhp);
          mma_bf16(acc[mt][nt], ah[mt], blp);
          mma_bf16(acc[mt][nt], al[mt], bhp);
        }
    }
  }

  if (mode == 0) {
    const int erow = bm + wm * 32 + (lane >> 2);
    const int ecol = bn + wn * 64 + (lane & 3) * 2;
#pragma unroll
    for (int mt = 0; mt < 2; ++mt)
#pragma unroll
      for (int nt = 0; nt < 8; ++nt) {
        float* c = acc[mt][nt];
        float* p0 = C + (size_t)(erow + mt * 16) * D + ecol + nt * 8;
        *(float2*)p0 = make_float2(c[0], c[1]);
        *(float2*)(p0 + 8 * D) = make_float2(c[2], c[3]);
      }
    return;
  }

  const int b = bm >> 11;                       // L = 2048
  const int seq0 = (bm & 2047) + wm * 32 + (lane >> 2);
  const int head = (bn >> 6) + wn;
  const int bh = b * H + head;
  const int d0 = (lane & 3) * 2;

  if (mode == 1) {
#pragma unroll
    for (int mt = 0; mt < 2; ++mt)
#pragma unroll
      for (int nt = 0; nt < 8; ++nt) {
        float* c = acc[mt][nt];
        const int d = d0 + nt * 8;
        const int s0 = seq0 + mt * 16;
        uint32_t hi, lo;
        pack_hl(c[0] * scale, c[1] * scale, hi, lo);
        size_t idx = ((size_t)bh * L + s0) * DH + d;
        *(uint32_t*)(outH + idx) = hi;
        *(uint32_t*)(outL + idx) = lo;
        pack_hl(c[2] * scale, c[3] * scale, hi, lo);
        idx = ((size_t)bh * L + s0 + 8) * DH + d;
        *(uint32_t*)(outH + idx) = hi;
        *(uint32_t*)(outL + idx) = lo;
      }
  } else {  // mode 2: transposed V
#pragma unroll
    for (int mt = 0; mt < 2; ++mt)
#pragma unroll
      for (int nt = 0; nt < 8; ++nt) {
        float* c = acc[mt][nt];
        const int d = d0 + nt * 8;
        const int s0 = seq0 + mt * 16;
#pragma unroll
        for (int e = 0; e < 4; ++e) {
          const int dd = d + (e & 1);
          const int ss = s0 + (e >> 1) * 8;
          __nv_bfloat16 h = __float2bfloat16_rn(c[e]);
          __nv_bfloat16 l = __float2bfloat16_rn(c[e] - __bfloat162float(h));
          size_t idx = ((size_t)bh * DH + dd) * L + ss;
          outH[idx] = h;
          outL[idx] = l;
        }
      }
  }
}

// ---------------------------------------------------------------------------
// Flash attention: pre-converted bf16 hi/lo inputs, 64 q-rows / 128 threads.
// smem: QH/QL [64x64], KH/KL [64x64], VH/VL [64(dh)x64(key)] (all bf16,
// 128B rows, SW128), kpm[64].
// ---------------------------------------------------------------------------
namespace aoff {
constexpr int QHI = 0, QLO = 8192, KHI = 16384, KLO = 24576,
              VHI = 32768, VLO = 40960, KPM = 49152, TOTAL = 49152 + 256;
}

__global__ __launch_bounds__(128, 3) void attn_mma_kernel(
    const float* __restrict__ attn_mask, const int* __restrict__ kpm) {
  using namespace cfg;
  extern __shared__ char smem[];
  const uint32_t sb = smem_u32(smem);
  int* kpm_s = (int*)(smem + aoff::KPM);
  const int tid = threadIdx.x;
  const int w = tid >> 5, lane = tid & 31;
  const int qt = blockIdx.x, h = blockIdx.y, b = blockIdx.z;
  const int bh = b * H + h;

  const float L2E = 1.44269504088896f;

  // copy mapping: row = tid>>1 (0..63), half = tid&1 (4 x uint4 = 64B).
  const int crow = tid >> 1, chalf = tid & 1;

  // ---- Q tile copy (already scaled by QSC in GEMM epilogue) ----
  {
    const uint4* srcH = (const uint4*)(g_Qh + ((size_t)bh * L + qt * 64 + crow) * DH);
    const uint4* srcL = (const uint4*)(g_Ql + ((size_t)bh * L + qt * 64 + crow) * DH);
#pragma unroll
    for (int j = 0; j < 4; ++j) {
      uint32_t off = SW128((uint32_t)crow * 128 + (uint32_t)(chalf * 4 + j) * 16);
      *(uint4*)(smem + aoff::QHI + off) = srcH[chalf * 4 + j];
      *(uint4*)(smem + aoff::QLO + off) = srcL[chalf * 4 + j];
    }
  }
  __syncthreads();

  const int l7 = lane & 7;
  const uint32_t a_row = (uint32_t)(w * 16 + (lane & 15));
  const uint32_t a_colb = (uint32_t)((lane >> 4) * 16);
  const uint32_t b_row = (uint32_t)(l7 + ((lane >> 4) & 1) * 8);
  const uint32_t b_colb = (uint32_t)(((lane >> 3) & 1) * 16);

  uint32_t qh[4][4], ql[4][4];
#pragma unroll
  for (int ks = 0; ks < 4; ++ks) {
    uint32_t off = SW128(a_row * 128 + (uint32_t)ks * 32 + a_colb);
    ldm_x4(qh[ks][0], qh[ks][1], qh[ks][2], qh[ks][3], sb + aoff::QHI + off);
    ldm_x4(ql[ks][0], ql[ks][1], ql[ks][2], ql[ks][3], sb + aoff::QLO + off);
  }

  float m0 = -1e30f, m1 = -1e30f, l0 = 0.0f, l1 = 0.0f;
  float O[8][4];
#pragma unroll
  for (int nt = 0; nt < 8; ++nt)
#pragma unroll
    for (int q = 0; q < 4; ++q) O[nt][q] = 0.0f;

  const int r0g = qt * 64 + w * 16 + (lane >> 2);

  for (int kt = 0; kt < 32; ++kt) {
    __syncthreads();
    // K tile copy [64 key x 64 dh] hi/lo; Vt tile copy [64 dh x 64 key].
    {
      const uint4* kH = (const uint4*)(g_Kh + ((size_t)bh * L + kt * 64 + crow) * DH);
      const uint4* kL = (const uint4*)(g_Kl + ((size_t)bh * L + kt * 64 + crow) * DH);
      const uint4* vH = (const uint4*)(g_Vth + ((size_t)bh * DH + crow) * L + kt * 64);
      const uint4* vL = (const uint4*)(g_Vtl + ((size_t)bh * DH + crow) * L + kt * 64);
#pragma unroll
      for (int j = 0; j < 4; ++j) {
        uint32_t off = SW128((uint32_t)crow * 128 + (uint32_t)(chalf * 4 + j) * 16);
        *(uint4*)(smem + aoff::KHI + off) = kH[chalf * 4 + j];
        *(uint4*)(smem + aoff::KLO + off) = kL[chalf * 4 + j];
        *(uint4*)(smem + aoff::VHI + off) = vH[chalf * 4 + j];
        *(uint4*)(smem + aoff::VLO + off) = vL[chalf * 4 + j];
      }
      if (tid < 64) kpm_s[tid] = kpm[b * L + kt * 64 + tid];
    }
    __syncthreads();

    // Mask preload (x log2e).
    float2 mv0[8], mv1[8];
    {
      const int colg = kt * 64 + 2 * (lane & 3);
      const float* mrow0 = attn_mask + (size_t)r0g * L + colg;
      const float* mrow1 = attn_mask + (size_t)(r0g + 8) * L + colg;
#pragma unroll
      for (int nt = 0; nt < 8; ++nt) {
        float2 a = *(const float2*)(mrow0 + nt * 8);
        float2 c = *(const float2*)(mrow1 + nt * 8);
        mv0[nt] = make_float2(a.x * L2E, a.y * L2E);
        mv1[nt] = make_float2(c.x * L2E, c.y * L2E);
      }
    }

    // S = Q K^T (3-pass hi/lo), log2 units.
    float S[8][4];
#pragma unroll
    for (int nt = 0; nt < 8; ++nt)
#pragma unroll
      for (int q = 0; q < 4; ++q) S[nt][q] = 0.0f;

#pragma unroll
    for (int ks = 0; ks < 4; ++ks) {
      uint32_t kh[4][4], kl[4][4];
#pragma unroll
      for (int p = 0; p < 4; ++p) {
        uint32_t off = SW128(((uint32_t)p * 16 + b_row) * 128 + (uint32_t)ks * 32 + b_colb);
        ldm_x4(kh[p][0], kh[p][1], kh[p][2], kh[p][3], sb + aoff::KHI + off);
        ldm_x4(kl[p][0], kl[p][1], kl[p][2], kl[p][3], sb + aoff::KLO + off);
      }
#pragma unroll
      for (int nt = 0; nt < 8; ++nt) {
        const uint32_t* bhp = &kh[nt >> 1][(nt & 1) * 2];
        const uint32_t* blp = &kl[nt >> 1][(nt & 1) * 2];
        mma_bf16(S[nt], qh[ks], bhp);
        mma_bf16(S[nt], qh[ks], blp);
        mma_bf16(S[nt], ql[ks], bhp);
      }
    }

    // mask + padding + online softmax (log2 domain, quad shfl).
    float tmax0 = -1e30f, tmax1 = -1e30f;
#pragma unroll
    for (int nt = 0; nt < 8; ++nt) {
      const int c = nt * 8 + 2 * (lane & 3);
      const bool p0 = (kpm_s[c] == 0), p1 = (kpm_s[c + 1] == 0);
      float sv0 = p0 ? -1e7f : (S[nt][0] + mv0[nt].x);
      float sv1 = p1 ? -1e7f : (S[nt][1] + mv0[nt].y);
      float sv2 = p0 ? -1e7f : (S[nt][2] + mv1[nt].x);
      float sv3 = p1 ? -1e7f : (S[nt][3] + mv1[nt].y);
      S[nt][0] = sv0; S[nt][1] = sv1; S[nt][2] = sv2; S[nt][3] = sv3;
      tmax0 = fmaxf(tmax0, fmaxf(sv0, sv1));
      tmax1 = fmaxf(tmax1, fmaxf(sv2, sv3));
    }
    tmax0 = fmaxf(tmax0, __shfl_xor_sync(0xffffffffu, tmax0, 1));
    tmax0 = fmaxf(tmax0, __shfl_xor_sync(0xffffffffu, tmax0, 2));
    tmax1 = fmaxf(tmax1, __shfl_xor_sync(0xffffffffu, tmax1, 1));
    tmax1 = fmaxf(tmax1, __shfl_xor_sync(0xffffffffu, tmax1, 2));

    const float mn0 = fmaxf(m0, tmax0), mn1 = fmaxf(m1, tmax1);
    const float alpha0 = fast_exp2(m0 - mn0), alpha1 = fast_exp2(m1 - mn1);
    float rs0 = 0.0f, rs1 = 0.0f;
#pragma unroll
    for (int nt = 0; nt < 8; ++nt) {
      float p0 = fast_exp2(S[nt][0] - mn0);
      float p1 = fast_exp2(S[nt][1] - mn0);
      float p2 = fast_exp2(S[nt][2] - mn1);
      float p3 = fast_exp2(S[nt][3] - mn1);
      S[nt][0] = p0; S[nt][1] = p1; S[nt][2] = p2; S[nt][3] = p3;
      rs0 += p0 + p1;
      rs1 += p2 + p3;
      O[nt][0] *= alpha0; O[nt][1] *= alpha0;
      O[nt][2] *= alpha1; O[nt][3] *= alpha1;
    }
    rs0 += __shfl_xor_sync(0xffffffffu, rs0, 1);
    rs0 += __shfl_xor_sync(0xffffffffu, rs0, 2);
    rs1 += __shfl_xor_sync(0xffffffffu, rs1, 1);
    rs1 += __shfl_xor_sync(0xffffffffu, rs1, 2);
    l0 = l0 * alpha0 + rs0; m0 = mn0;
    l1 = l1 * alpha1 + rs1; m1 = mn1;

    // O += P V (P packed hi/lo from registers).
#pragma unroll
    for (int t = 0; t < 4; ++t) {
      uint32_t ah[4], al[4];
      pack_hl(S[2 * t][0], S[2 * t][1], ah[0], al[0]);
      pack_hl(S[2 * t][2], S[2 * t][3], ah[1], al[1]);
      pack_hl(S[2 * t + 1][0], S[2 * t + 1][1], ah[2], al[2]);
      pack_hl(S[2 * t + 1][2], S[2 * t + 1][3], ah[3], al[3]);
      uint32_t vh[4][4], vl[4][4];
#pragma unroll
      for (int p = 0; p < 4; ++p) {
        uint32_t off = SW128(((uint32_t)p * 16 + b_row) * 128 + (uint32_t)t * 32 + b_colb);
        ldm_x4(vh[p][0], vh[p][1], vh[p][2], vh[p][3], sb + aoff::VHI + off);
        ldm_x4(vl[p][0], vl[p][1], vl[p][2], vl[p][3], sb + aoff::VLO + off);
      }
#pragma unroll
      for (int nt = 0; nt < 8; ++nt) {
        const uint32_t* bhp = &vh[nt >> 1][(nt & 1) * 2];
        const uint32_t* blp = &vl[nt >> 1][(nt & 1) * 2];
        mma_bf16(O[nt], ah, bhp);
        mma_bf16(O[nt], ah, blp);
        mma_bf16(O[nt], al, bhp);
      }
    }
  }

  const float inv0 = 1.0f / l0, inv1 = 1.0f / l1;
  float* Og = g_A + (size_t)(b * L + r0g) * D + h * DH + 2 * (lane & 3);
#pragma unroll
  for (int nt = 0; nt < 8; ++nt) {
    *(float2*)(Og + nt * 8) = make_float2(O[nt][0] * inv0, O[nt][1] * inv0);
    *(float2*)(Og + 8 * D + nt * 8) = make_float2(O[nt][2] * inv1, O[nt][3] * inv1);
  }
}

// ---------------------------------------------------------------------------
extern "C" void kernel_launch(void* const* d_in, const int* in_sizes, int n_in,
                              void* d_out, int out_size) {
  using namespace cfg;
  (void)in_sizes; (void)n_in; (void)out_size;

  const float* query = (const float*)d_in[0];
  const float* key   = (const float*)d_in[1];
  const float* value = (const float*)d_in[2];
  const int* kpm     = (const int*)d_in[3];
  const float* mask  = (const float*)d_in[4];
  const float* Wq    = (const float*)d_in[5];
  const float* Wk    = (const float*)d_in[6];
  const float* Wv    = (const float*)d_in[7];
  const float* Wo    = (const float*)d_in[8];
  float* out = (float*)d_out;

  float* Ap;
  __nv_bfloat16 *Qh, *Ql, *Kh, *Kl, *Vth, *Vtl;
  cudaGetSymbolAddress((void**)&Ap, g_A);
  cudaGetSymbolAddress((void**)&Qh, g_Qh);
  cudaGetSymbolAddress((void**)&Ql, g_Ql);
  cudaGetSymbolAddress((void**)&Kh, g_Kh);
  cudaGetSymbolAddress((void**)&Kl, g_Kl);
  cudaGetSymbolAddress((void**)&Vth, g_Vth);
  cudaGetSymbolAddress((void**)&Vtl, g_Vtl);

  cudaFuncSetAttribute(gemm_mma_kernel,
                       cudaFuncAttributeMaxDynamicSharedMemorySize, goff::TOTAL);
  cudaFuncSetAttribute(attn_mma_kernel,
                       cudaFuncAttributeMaxDynamicSharedMemorySize, aoff::TOTAL);

  const float QSC = 0.03125f * 1.44269504088896f;  // scale * log2(e)

  dim3 gg(D / 128, M / 128);  // (8, 32)
  gemm_mma_kernel<<<gg, 256, goff::TOTAL>>>(query, Wq, nullptr, Qh, Ql, 1, QSC);
  gemm_mma_kernel<<<gg, 256, goff::TOTAL>>>(key,   Wk, nullptr, Kh, Kl, 1, 1.0f);
  gemm_mma_kernel<<<gg, 256, goff::TOTAL>>>(value, Wv, nullptr, Vth, Vtl, 2, 1.0f);

  attn_mma_kernel<<<dim3(L / 64, H, B), 128, aoff::TOTAL>>>(mask, kpm);

  gemm_mma_kernel<<<gg, 256, goff::TOTAL>>>(Ap, Wo, out, nullptr, nullptr, 0, 1.0f);
}

// round 8
// speedup vs baseline: 1.1652x; 1.1652x over previous
#include <cuda_runtime.h>
#include <cuda_bf16.h>
#include <cstdint>

// ---------------------------------------------------------------------------
// MHA: B=2, L=2048, D=1024, H=16, dh=64.
// R6: GEMMs reverted to clean fp32-out (R4 form). Q/K/V bf16 hi/lo conversion
//     moved to dedicated coalesced convert kernels (streaming + smem
//     transpose). Attention identical to R5 (514us measured).
// ---------------------------------------------------------------------------

namespace cfg {
constexpr int B = 2;
constexpr int L = 2048;
constexpr int D = 1024;
constexpr int H = 16;
constexpr int DH = 64;
constexpr int M = B * L;
constexpr int BH = B * H;
}

__device__ float g_Q[(size_t)cfg::B * cfg::L * cfg::D];
__device__ float g_K[(size_t)cfg::B * cfg::L * cfg::D];
__device__ float g_V[(size_t)cfg::B * cfg::L * cfg::D];
__device__ float g_A[(size_t)cfg::B * cfg::L * cfg::D];
__device__ __nv_bfloat16 g_Qh[(size_t)cfg::BH * cfg::L * cfg::DH];
__device__ __nv_bfloat16 g_Ql[(size_t)cfg::BH * cfg::L * cfg::DH];
__device__ __nv_bfloat16 g_Kh[(size_t)cfg::BH * cfg::L * cfg::DH];
__device__ __nv_bfloat16 g_Kl[(size_t)cfg::BH * cfg::L * cfg::DH];
__device__ __nv_bfloat16 g_Vth[(size_t)cfg::BH * cfg::DH * cfg::L];  // [dh][seq]
__device__ __nv_bfloat16 g_Vtl[(size_t)cfg::BH * cfg::DH * cfg::L];

// ======================= portable tensor-core helpers ======================
__device__ __forceinline__ uint32_t smem_u32(const void* p) {
  uint32_t a;
  asm("{ .reg .u64 t; cvta.to.shared.u64 t, %1; cvt.u32.u64 %0, t; }"
      : "=r"(a) : "l"(p));
  return a;
}

__device__ __forceinline__ void ldm_x4(uint32_t& r0, uint32_t& r1,
                                       uint32_t& r2, uint32_t& r3,
                                       uint32_t addr) {
  asm volatile("ldmatrix.sync.aligned.m8n8.x4.shared.b16 {%0,%1,%2,%3}, [%4];"
               : "=r"(r0), "=r"(r1), "=r"(r2), "=r"(r3) : "r"(addr));
}

__device__ __forceinline__ void mma_bf16(float* c, const uint32_t* a,
                                         const uint32_t* b) {
  asm volatile(
      "mma.sync.aligned.m16n8k16.row.col.f32.bf16.bf16.f32 "
      "{%0,%1,%2,%3}, {%4,%5,%6,%7}, {%8,%9}, {%0,%1,%2,%3};"
      : "+f"(c[0]), "+f"(c[1]), "+f"(c[2]), "+f"(c[3])
      : "r"(a[0]), "r"(a[1]), "r"(a[2]), "r"(a[3]), "r"(b[0]), "r"(b[1]));
}

__device__ __forceinline__ float fast_exp2(float x) {
  float y;
  asm("ex2.approx.f32 %0, %1;" : "=f"(y) : "f"(x));
  return y;
}

#define SW128(off) ((off) ^ ((((uint32_t)(off)) >> 3) & 0x70))

__device__ __forceinline__ uint32_t pack_bf2(float a, float b) {
  __nv_bfloat162 h = __floats2bfloat162_rn(a, b);
  return *(uint32_t*)&h;
}
__device__ __forceinline__ void pack_hl(float a, float b, uint32_t& hi,
                                        uint32_t& lo) {
  __nv_bfloat162 h = __floats2bfloat162_rn(a, b);
  hi = *(uint32_t*)&h;
  lo = pack_bf2(a - __bfloat162float(h.x), b - __bfloat162float(h.y));
}

// ---------------------------------------------------------------------------
// Projection GEMM (R4 form): C[M,1024] = A[M,1024] @ W[1024,1024]^T.
// ---------------------------------------------------------------------------
namespace goff {
constexpr int AHI = 0, ALO = 16384, BHI = 32768, BLO = 49152, TOTAL = 65536;
}

__global__ __launch_bounds__(256) void gemm_mma_kernel(
    const float* __restrict__ A, const float* __restrict__ W,
    float* __restrict__ C) {
  using namespace cfg;
  extern __shared__ char smem[];
  const uint32_t sb = smem_u32(smem);
  const int tid = threadIdx.x;
  const int wid = tid >> 5, lane = tid & 31;
  const int wm = wid & 3;
  const int wn = wid >> 2;
  const int bm = blockIdx.y << 7;
  const int bn = blockIdx.x << 7;

  const int lrow = tid >> 2;
  const int lk = (tid & 3) << 4;

  const float* Ap = A + (size_t)(bm + lrow) * D + lk;
  const float* Wp = W + (size_t)(bn + lrow) * D + lk;

  const uint32_t st0 = (uint32_t)lrow * 128 + (uint32_t)lk * 2;

  const int l7 = lane & 7;
  const uint32_t a_row_off = (uint32_t)(wm * 32 + l7 + ((lane >> 3) & 1) * 8) * 128;
  const uint32_t a_col_off = (uint32_t)((lane >> 4) * 16);
  const uint32_t b_row_off = (uint32_t)(wn * 64 + l7 + ((lane >> 4) & 1) * 8) * 128;
  const uint32_t b_col_off = (uint32_t)(((lane >> 3) & 1) * 16);

  float acc[2][8][4];
#pragma unroll
  for (int mt = 0; mt < 2; ++mt)
#pragma unroll
    for (int nt = 0; nt < 8; ++nt)
#pragma unroll
      for (int q = 0; q < 4; ++q) acc[mt][nt][q] = 0.0f;

  for (int ch = 0; ch < 16; ++ch) {
    const int k0 = ch << 6;

    float4 av[2][4], wv[2][4];
#pragma unroll
    for (int ri = 0; ri < 2; ++ri) {
      const float* ap = Ap + (size_t)ri * 64 * D + k0;
      const float* wp = Wp + (size_t)ri * 64 * D + k0;
#pragma unroll
      for (int i = 0; i < 4; ++i) {
        av[ri][i] = *(const float4*)(ap + i * 4);
        wv[ri][i] = *(const float4*)(wp + i * 4);
      }
    }

    __syncthreads();

#pragma unroll
    for (int ri = 0; ri < 2; ++ri) {
      const uint32_t so = st0 + (uint32_t)ri * 64 * 128;
#pragma unroll
      for (int half = 0; half < 2; ++half) {
        float4 v0a = av[ri][half * 2], v1a = av[ri][half * 2 + 1];
        float4 v0w = wv[ri][half * 2], v1w = wv[ri][half * 2 + 1];
        uint32_t off = SW128(so + half * 16);

        uint4 hi_a, lo_a, hi_w, lo_w;
        pack_hl(v0a.x, v0a.y, hi_a.x, lo_a.x);
        pack_hl(v0a.z, v0a.w, hi_a.y, lo_a.y);
        pack_hl(v1a.x, v1a.y, hi_a.z, lo_a.z);
        pack_hl(v1a.z, v1a.w, hi_a.w, lo_a.w);
        pack_hl(v0w.x, v0w.y, hi_w.x, lo_w.x);
        pack_hl(v0w.z, v0w.w, hi_w.y, lo_w.y);
        pack_hl(v1w.x, v1w.y, hi_w.z, lo_w.z);
        pack_hl(v1w.z, v1w.w, hi_w.w, lo_w.w);
        *(uint4*)(smem + goff::AHI + off) = hi_a;
        *(uint4*)(smem + goff::ALO + off) = lo_a;
        *(uint4*)(smem + goff::BHI + off) = hi_w;
        *(uint4*)(smem + goff::BLO + off) = lo_w;
      }
    }
    __syncthreads();

#pragma unroll
    for (int ks = 0; ks < 4; ++ks) {
      const uint32_t kc = (uint32_t)ks * 32;
      uint32_t ah[2][4], al[2][4], bh[4][4], bl[4][4];
#pragma unroll
      for (int mt = 0; mt < 2; ++mt) {
        uint32_t o = a_row_off + (uint32_t)mt * 16 * 128 + kc + a_col_off;
        uint32_t sw = SW128(o);
        ldm_x4(ah[mt][0], ah[mt][1], ah[mt][2], ah[mt][3], sb + goff::AHI + sw);
        ldm_x4(al[mt][0], al[mt][1], al[mt][2], al[mt][3], sb + goff::ALO + sw);
      }
#pragma unroll
      for (int p = 0; p < 4; ++p) {
        uint32_t o = b_row_off + (uint32_t)p * 16 * 128 + kc + b_col_off;
        uint32_t sw = SW128(o);
        ldm_x4(bh[p][0], bh[p][1], bh[p][2], bh[p][3], sb + goff::BHI + sw);
        ldm_x4(bl[p][0], bl[p][1], bl[p][2], bl[p][3], sb + goff::BLO + sw);
      }
#pragma unroll
      for (int mt = 0; mt < 2; ++mt)
#pragma unroll
        for (int nt = 0; nt < 8; ++nt) {
          const uint32_t* bhp = &bh[nt >> 1][(nt & 1) * 2];
          const uint32_t* blp = &bl[nt >> 1][(nt & 1) * 2];
          mma_bf16(acc[mt][nt], ah[mt], bhp);
          mma_bf16(acc[mt][nt], ah[mt], blp);
          mma_bf16(acc[mt][nt], al[mt], bhp);
        }
    }
  }

  const int erow = bm + wm * 32 + (lane >> 2);
  const int ecol = bn + wn * 64 + (lane & 3) * 2;
#pragma unroll
  for (int mt = 0; mt < 2; ++mt)
#pragma unroll
    for (int nt = 0; nt < 8; ++nt) {
      float* c = acc[mt][nt];
      float* p0 = C + (size_t)(erow + mt * 16) * D + ecol + nt * 8;
      *(float2*)p0 = make_float2(c[0], c[1]);
      *(float2*)(p0 + 8 * D) = make_float2(c[2], c[3]);
    }
}

// ---------------------------------------------------------------------------
// convert_qk: fp32 [b, l, h*64] -> bf16 hi/lo [(b*h), l, 64], scaled.
// One float4 per thread; fully coalesced.
// ---------------------------------------------------------------------------
__global__ __launch_bounds__(256) void convert_qk_kernel(
    const float* __restrict__ src, __nv_bfloat16* __restrict__ outH,
    __nv_bfloat16* __restrict__ outL, float scale) {
  using namespace cfg;
  const size_t i4 = (size_t)blockIdx.x * blockDim.x + threadIdx.x;
  const size_t f = i4 * 4;  // element index; total B*L*D
  const int b = (int)(f >> 21);            // / (L*D) = /2^21
  const int l = (int)((f >> 10) & 2047);   // / D % L
  const int d = (int)(f & 1023);
  const int h = d >> 6, dd = d & 63;

  float4 v = *(const float4*)(src + f);
  uint32_t h0, l0v, h1, l1v;
  pack_hl(v.x * scale, v.y * scale, h0, l0v);
  pack_hl(v.z * scale, v.w * scale, h1, l1v);

  const size_t o = (((size_t)(b * H + h) * L) + l) * DH + dd;
  *(uint2*)(outH + o) = make_uint2(h0, h1);
  *(uint2*)(outL + o) = make_uint2(l0v, l1v);
}

// ---------------------------------------------------------------------------
// convert_v: fp32 [b, l, h*64] -> bf16 hi/lo transposed [(b*h), 64(dh), L].
// Tile 64 seq x 64 dh via smem. grid=(L/64, BH), 256 threads.
// ---------------------------------------------------------------------------
__global__ __launch_bounds__(256) void convert_v_kernel(
    const float* __restrict__ src, __nv_bfloat16* __restrict__ outH,
    __nv_bfloat16* __restrict__ outL) {
  using namespace cfg;
  __shared__ float tile[64][65];
  const int tid = threadIdx.x;
  const int st = blockIdx.x;        // seq tile
  const int bh = blockIdx.y;
  const int b = bh >> 4, h = bh & 15;

  // Load: 64 rows x 64 cols fp32; thread reads 16 floats (4 float4).
  const int lrow = tid >> 2, lcol = (tid & 3) << 4;
  const float* sp = src + ((size_t)(b * L + st * 64 + lrow) << 10) + h * DH + lcol;
#pragma unroll
  for (int i = 0; i < 4; ++i) {
    float4 v = *(const float4*)(sp + i * 4);
    tile[lrow][lcol + i * 4 + 0] = v.x;
    tile[lrow][lcol + i * 4 + 1] = v.y;
    tile[lrow][lcol + i * 4 + 2] = v.z;
    tile[lrow][lcol + i * 4 + 3] = v.w;
  }
  __syncthreads();

  // Store transposed: thread owns (dh = tid>>2, 16 seq = (tid&3)*16).
  const int dh = tid >> 2, s0 = (tid & 3) << 4;
  uint32_t hv[8], lv[8];
#pragma unroll
  for (int j = 0; j < 8; ++j)
    pack_hl(tile[s0 + 2 * j][dh], tile[s0 + 2 * j + 1][dh], hv[j], lv[j]);
  const size_t o = ((size_t)bh * DH + dh) * L + st * 64 + s0;
  *(uint4*)(outH + o) = *(uint4*)&hv[0];
  *(uint4*)(outH + o + 8) = *(uint4*)&hv[4];
  *(uint4*)(outL + o) = *(uint4*)&lv[0];
  *(uint4*)(outL + o + 8) = *(uint4*)&lv[4];
}

// ---------------------------------------------------------------------------
// Flash attention (identical to R5): pre-converted bf16 hi/lo inputs.
// ---------------------------------------------------------------------------
namespace aoff {
constexpr int QHI = 0, QLO = 8192, KHI = 16384, KLO = 24576,
              VHI = 32768, VLO = 40960, KPM = 49152, TOTAL = 49152 + 256;
}

__global__ __launch_bounds__(128, 3) void attn_mma_kernel(
    const float* __restrict__ attn_mask, const int* __restrict__ kpm) {
  using namespace cfg;
  extern __shared__ char smem[];
  const uint32_t sb = smem_u32(smem);
  int* kpm_s = (int*)(smem + aoff::KPM);
  const int tid = threadIdx.x;
  const int w = tid >> 5, lane = tid & 31;
  const int qt = blockIdx.x, h = blockIdx.y, b = blockIdx.z;
  const int bh = b * H + h;

  const float L2E = 1.44269504088896f;
  const int crow = tid >> 1, chalf = tid & 1;

  {
    const uint4* srcH = (const uint4*)(g_Qh + ((size_t)bh * L + qt * 64 + crow) * DH);
    const uint4* srcL = (const uint4*)(g_Ql + ((size_t)bh * L + qt * 64 + crow) * DH);
#pragma unroll
    for (int j = 0; j < 4; ++j) {
      uint32_t off = SW128((uint32_t)crow * 128 + (uint32_t)(chalf * 4 + j) * 16);
      *(uint4*)(smem + aoff::QHI + off) = srcH[chalf * 4 + j];
      *(uint4*)(smem + aoff::QLO + off) = srcL[chalf * 4 + j];
    }
  }
  __syncthreads();

  const int l7 = lane & 7;
  const uint32_t a_row = (uint32_t)(w * 16 + (lane & 15));
  const uint32_t a_colb = (uint32_t)((lane >> 4) * 16);
  const uint32_t b_row = (uint32_t)(l7 + ((lane >> 4) & 1) * 8);
  const uint32_t b_colb = (uint32_t)(((lane >> 3) & 1) * 16);

  uint32_t qh[4][4], ql[4][4];
#pragma unroll
  for (int ks = 0; ks < 4; ++ks) {
    uint32_t off = SW128(a_row * 128 + (uint32_t)ks * 32 + a_colb);
    ldm_x4(qh[ks][0], qh[ks][1], qh[ks][2], qh[ks][3], sb + aoff::QHI + off);
    ldm_x4(ql[ks][0], ql[ks][1], ql[ks][2], ql[ks][3], sb + aoff::QLO + off);
  }

  float m0 = -1e30f, m1 = -1e30f, l0 = 0.0f, l1 = 0.0f;
  float O[8][4];
#pragma unroll
  for (int nt = 0; nt < 8; ++nt)
#pragma unroll
    for (int q = 0; q < 4; ++q) O[nt][q] = 0.0f;

  const int r0g = qt * 64 + w * 16 + (lane >> 2);

  for (int kt = 0; kt < 32; ++kt) {
    __syncthreads();
    {
      const uint4* kH = (const uint4*)(g_Kh + ((size_t)bh * L + kt * 64 + crow) * DH);
      const uint4* kL = (const uint4*)(g_Kl + ((size_t)bh * L + kt * 64 + crow) * DH);
      const uint4* vH = (const uint4*)(g_Vth + ((size_t)bh * DH + crow) * L + kt * 64);
      const uint4* vL = (const uint4*)(g_Vtl + ((size_t)bh * DH + crow) * L + kt * 64);
#pragma unroll
      for (int j = 0; j < 4; ++j) {
        uint32_t off = SW128((uint32_t)crow * 128 + (uint32_t)(chalf * 4 + j) * 16);
        *(uint4*)(smem + aoff::KHI + off) = kH[chalf * 4 + j];
        *(uint4*)(smem + aoff::KLO + off) = kL[chalf * 4 + j];
        *(uint4*)(smem + aoff::VHI + off) = vH[chalf * 4 + j];
        *(uint4*)(smem + aoff::VLO + off) = vL[chalf * 4 + j];
      }
      if (tid < 64) kpm_s[tid] = kpm[b * L + kt * 64 + tid];
    }
    __syncthreads();

    float2 mv0[8], mv1[8];
    {
      const int colg = kt * 64 + 2 * (lane & 3);
      const float* mrow0 = attn_mask + (size_t)r0g * L + colg;
      const float* mrow1 = attn_mask + (size_t)(r0g + 8) * L + colg;
#pragma unroll
      for (int nt = 0; nt < 8; ++nt) {
        float2 a = *(const float2*)(mrow0 + nt * 8);
        float2 c = *(const float2*)(mrow1 + nt * 8);
        mv0[nt] = make_float2(a.x * L2E, a.y * L2E);
        mv1[nt] = make_float2(c.x * L2E, c.y * L2E);
      }
    }

    float S[8][4];
#pragma unroll
    for (int nt = 0; nt < 8; ++nt)
#pragma unroll
      for (int q = 0; q < 4; ++q) S[nt][q] = 0.0f;

#pragma unroll
    for (int ks = 0; ks < 4; ++ks) {
      uint32_t kh[4][4], kl[4][4];
#pragma unroll
      for (int p = 0; p < 4; ++p) {
        uint32_t off = SW128(((uint32_t)p * 16 + b_row) * 128 + (uint32_t)ks * 32 + b_colb);
        ldm_x4(kh[p][0], kh[p][1], kh[p][2], kh[p][3], sb + aoff::KHI + off);
        ldm_x4(kl[p][0], kl[p][1], kl[p][2], kl[p][3], sb + aoff::KLO + off);
      }
#pragma unroll
      for (int nt = 0; nt < 8; ++nt) {
        const uint32_t* bhp = &kh[nt >> 1][(nt & 1) * 2];
        const uint32_t* blp = &kl[nt >> 1][(nt & 1) * 2];
        mma_bf16(S[nt], qh[ks], bhp);
        mma_bf16(S[nt], qh[ks], blp);
        mma_bf16(S[nt], ql[ks], bhp);
      }
    }

    float tmax0 = -1e30f, tmax1 = -1e30f;
#pragma unroll
    for (int nt = 0; nt < 8; ++nt) {
      const int c = nt * 8 + 2 * (lane & 3);
      const bool p0 = (kpm_s[c] == 0), p1 = (kpm_s[c + 1] == 0);
      float sv0 = p0 ? -1e7f : (S[nt][0] + mv0[nt].x);
      float sv1 = p1 ? -1e7f : (S[nt][1] + mv0[nt].y);
      float sv2 = p0 ? -1e7f : (S[nt][2] + mv1[nt].x);
      float sv3 = p1 ? -1e7f : (S[nt][3] + mv1[nt].y);
      S[nt][0] = sv0; S[nt][1] = sv1; S[nt][2] = sv2; S[nt][3] = sv3;
      tmax0 = fmaxf(tmax0, fmaxf(sv0, sv1));
      tmax1 = fmaxf(tmax1, fmaxf(sv2, sv3));
    }
    tmax0 = fmaxf(tmax0, __shfl_xor_sync(0xffffffffu, tmax0, 1));
    tmax0 = fmaxf(tmax0, __shfl_xor_sync(0xffffffffu, tmax0, 2));
    tmax1 = fmaxf(tmax1, __shfl_xor_sync(0xffffffffu, tmax1, 1));
    tmax1 = fmaxf(tmax1, __shfl_xor_sync(0xffffffffu, tmax1, 2));

    const float mn0 = fmaxf(m0, tmax0), mn1 = fmaxf(m1, tmax1);
    const float alpha0 = fast_exp2(m0 - mn0), alpha1 = fast_exp2(m1 - mn1);
    float rs0 = 0.0f, rs1 = 0.0f;
#pragma unroll
    for (int nt = 0; nt < 8; ++nt) {
      float p0 = fast_exp2(S[nt][0] - mn0);
      float p1 = fast_exp2(S[nt][1] - mn0);
      float p2 = fast_exp2(S[nt][2] - mn1);
      float p3 = fast_exp2(S[nt][3] - mn1);
      S[nt][0] = p0; S[nt][1] = p1; S[nt][2] = p2; S[nt][3] = p3;
      rs0 += p0 + p1;
      rs1 += p2 + p3;
      O[nt][0] *= alpha0; O[nt][1] *= alpha0;
      O[nt][2] *= alpha1; O[nt][3] *= alpha1;
    }
    rs0 += __shfl_xor_sync(0xffffffffu, rs0, 1);
    rs0 += __shfl_xor_sync(0xffffffffu, rs0, 2);
    rs1 += __shfl_xor_sync(0xffffffffu, rs1, 1);
    rs1 += __shfl_xor_sync(0xffffffffu, rs1, 2);
    l0 = l0 * alpha0 + rs0; m0 = mn0;
    l1 = l1 * alpha1 + rs1; m1 = mn1;

#pragma unroll
    for (int t = 0; t < 4; ++t) {
      uint32_t ah[4], al[4];
      pack_hl(S[2 * t][0], S[2 * t][1], ah[0], al[0]);
      pack_hl(S[2 * t][2], S[2 * t][3], ah[1], al[1]);
      pack_hl(S[2 * t + 1][0], S[2 * t + 1][1], ah[2], al[2]);
      pack_hl(S[2 * t + 1][2], S[2 * t + 1][3], ah[3], al[3]);
      uint32_t vh[4][4], vl[4][4];
#pragma unroll
      for (int p = 0; p < 4; ++p) {
        uint32_t off = SW128(((uint32_t)p * 16 + b_row) * 128 + (uint32_t)t * 32 + b_colb);
        ldm_x4(vh[p][0], vh[p][1], vh[p][2], vh[p][3], sb + aoff::VHI + off);
        ldm_x4(vl[p][0], vl[p][1], vl[p][2], vl[p][3], sb + aoff::VLO + off);
      }
#pragma unroll
      for (int nt = 0; nt < 8; ++nt) {
        const uint32_t* bhp = &vh[nt >> 1][(nt & 1) * 2];
        const uint32_t* blp = &vl[nt >> 1][(nt & 1) * 2];
        mma_bf16(O[nt], ah, bhp);
        mma_bf16(O[nt], ah, blp);
        mma_bf16(O[nt], al, bhp);
      }
    }
  }

  const float inv0 = 1.0f / l0, inv1 = 1.0f / l1;
  float* Og = g_A + (size_t)(b * L + r0g) * D + h * DH + 2 * (lane & 3);
#pragma unroll
  for (int nt = 0; nt < 8; ++nt) {
    *(float2*)(Og + nt * 8) = make_float2(O[nt][0] * inv0, O[nt][1] * inv0);
    *(float2*)(Og + 8 * D + nt * 8) = make_float2(O[nt][2] * inv1, O[nt][3] * inv1);
  }
}

// ---------------------------------------------------------------------------
extern "C" void kernel_launch(void* const* d_in, const int* in_sizes, int n_in,
                              void* d_out, int out_size) {
  using namespace cfg;
  (void)in_sizes; (void)n_in; (void)out_size;

  const float* query = (const float*)d_in[0];
  const float* key   = (const float*)d_in[1];
  const float* value = (const float*)d_in[2];
  const int* kpm     = (const int*)d_in[3];
  const float* mask  = (const float*)d_in[4];
  const float* Wq    = (const float*)d_in[5];
  const float* Wk    = (const float*)d_in[6];
  const float* Wv    = (const float*)d_in[7];
  const float* Wo    = (const float*)d_in[8];
  float* out = (float*)d_out;

  float *Qp, *Kp, *Vp, *Ap;
  __nv_bfloat16 *Qh, *Ql, *Kh, *Kl, *Vth, *Vtl;
  cudaGetSymbolAddress((void**)&Qp, g_Q);
  cudaGetSymbolAddress((void**)&Kp, g_K);
  cudaGetSymbolAddress((void**)&Vp, g_V);
  cudaGetSymbolAddress((void**)&Ap, g_A);
  cudaGetSymbolAddress((void**)&Qh, g_Qh);
  cudaGetSymbolAddress((void**)&Ql, g_Ql);
  cudaGetSymbolAddress((void**)&Kh, g_Kh);
  cudaGetSymbolAddress((void**)&Kl, g_Kl);
  cudaGetSymbolAddress((void**)&Vth, g_Vth);
  cudaGetSymbolAddress((void**)&Vtl, g_Vtl);

  cudaFuncSetAttribute(gemm_mma_kernel,
                       cudaFuncAttributeMaxDynamicSharedMemorySize, goff::TOTAL);
  cudaFuncSetAttribute(attn_mma_kernel,
                       cudaFuncAttributeMaxDynamicSharedMemorySize, aoff::TOTAL);

  const float QSC = 0.03125f * 1.44269504088896f;  // scale * log2(e)
  const int NCVT = (B * L * D / 4) / 256;          // 8192 blocks

  dim3 gg(D / 128, M / 128);  // (8, 32)
  gemm_mma_kernel<<<gg, 256, goff::TOTAL>>>(query, Wq, Qp);
  gemm_mma_kernel<<<gg, 256, goff::TOTAL>>>(key,   Wk, Kp);
  gemm_mma_kernel<<<gg, 256, goff::TOTAL>>>(value, Wv, Vp);

  convert_qk_kernel<<<NCVT, 256>>>(Qp, Qh, Ql, QSC);
  convert_qk_kernel<<<NCVT, 256>>>(Kp, Kh, Kl, 1.0f);
  convert_v_kernel<<<dim3(L / 64, BH), 256>>>(Vp, Vth, Vtl);

  attn_mma_kernel<<<dim3(L / 64, H, B), 128, aoff::TOTAL>>>(mask, kpm);

  gemm_mma_kernel<<<gg, 256, goff::TOTAL>>>(Ap, Wo, out);
}